// round 2
// baseline (speedup 1.0000x reference)
#include <cuda_runtime.h>
#include <math.h>

#define NPIX 4096   // H*W
#define NBH  4096   // B*HP

// Scratch (no allocation allowed -> __device__ globals)
__device__ float g_stats[NBH * 12];
__device__ float g_gate[NBH];
__device__ float g_row[NBH * 64];
__device__ float g_col[NBH * 64];
__device__ float g_drow[NBH * 64];
__device__ float g_dcol[NBH * 64];

__device__ __forceinline__ float wredsum(float v) {
#pragma unroll
    for (int o = 16; o; o >>= 1) v += __shfl_xor_sync(0xffffffffu, v, o);
    return v;
}
__device__ __forceinline__ float wredmax(float v) {
#pragma unroll
    for (int o = 16; o; o >>= 1) v = fmaxf(v, __shfl_xor_sync(0xffffffffu, v, o));
    return v;
}

// ============================================================================
// Kernel 1: per-(b,hp) statistics. One block per slice of 4096 elements.
// ============================================================================
__global__ __launch_bounds__(256) void k_stats(const float* __restrict__ a,
                                               const float* __restrict__ b) {
    const int slice = blockIdx.x;
    const float4* a4 = (const float4*)a + slice * (NPIX / 4);
    const float4* b4 = (const float4*)b + slice * (NPIX / 4);
    const int t = threadIdx.x;

    float sx = 0.f, sxx = 0.f, sy = 0.f, syy = 0.f, sxy = 0.f, sd = 0.f, sdd = 0.f;
    float mnx = INFINITY, mxx = -INFINITY, mny = INFINITY, mxy = -INFINITY;

    float4 va[4], vb[4];
#pragma unroll
    for (int k = 0; k < 4; k++) { va[k] = a4[t + k * 256]; vb[k] = b4[t + k * 256]; }
#pragma unroll
    for (int k = 0; k < 4; k++) {
        float xs[4] = {va[k].x, va[k].y, va[k].z, va[k].w};
        float ys[4] = {vb[k].x, vb[k].y, vb[k].z, vb[k].w};
#pragma unroll
        for (int e = 0; e < 4; e++) {
            float x = xs[e], y = ys[e];
            sx += x; sxx += x * x; sy += y; syy += y * y; sxy += x * y;
            float d = x - y; sd += d; sdd += d * d;
            mnx = fminf(mnx, x); mxx = fmaxf(mxx, x);
            mny = fminf(mny, y); mxy = fmaxf(mxy, y);
        }
    }

    sx = wredsum(sx); sxx = wredsum(sxx); sy = wredsum(sy); syy = wredsum(syy);
    sxy = wredsum(sxy); sd = wredsum(sd); sdd = wredsum(sdd);
    mnx = -wredmax(-mnx); mxx = wredmax(mxx);
    mny = -wredmax(-mny); mxy = wredmax(mxy);

    __shared__ float sh[8][11];
    const int wid = t >> 5, lane = t & 31;
    if (lane == 0) {
        float* r = sh[wid];
        r[0] = sx; r[1] = sxx; r[2] = sy; r[3] = syy; r[4] = sxy;
        r[5] = sd; r[6] = sdd; r[7] = mnx; r[8] = mxx; r[9] = mny; r[10] = mxy;
    }
    __syncthreads();
    if (t < 8) {
        float v0 = sh[t][0], v1 = sh[t][1], v2 = sh[t][2], v3 = sh[t][3], v4 = sh[t][4];
        float v5 = sh[t][5], v6 = sh[t][6];
        float m7 = sh[t][7], m8 = sh[t][8], m9 = sh[t][9], m10 = sh[t][10];
#pragma unroll
        for (int o = 4; o; o >>= 1) {
            v0 += __shfl_xor_sync(0xffu, v0, o);
            v1 += __shfl_xor_sync(0xffu, v1, o);
            v2 += __shfl_xor_sync(0xffu, v2, o);
            v3 += __shfl_xor_sync(0xffu, v3, o);
            v4 += __shfl_xor_sync(0xffu, v4, o);
            v5 += __shfl_xor_sync(0xffu, v5, o);
            v6 += __shfl_xor_sync(0xffu, v6, o);
            m7 = fminf(m7, __shfl_xor_sync(0xffu, m7, o));
            m8 = fmaxf(m8, __shfl_xor_sync(0xffu, m8, o));
            m9 = fminf(m9, __shfl_xor_sync(0xffu, m9, o));
            m10 = fmaxf(m10, __shfl_xor_sync(0xffu, m10, o));
        }
        if (t == 0) {
            const float N = 4096.f, NM1 = 4095.f;
            float mean_a = v0 / N;
            float std_a = sqrtf(fmaxf(0.f, (v1 - v0 * v0 / N) / NM1));
            float mean_b = v2 / N;
            float std_b = sqrtf(fmaxf(0.f, (v3 - v2 * v2 / N) / NM1));
            float mean_d = v5 / N;
            float std_d = sqrtf(fmaxf(0.f, (v6 - v5 * v5 / N) / NM1));
            float norm_d = sqrtf(fmaxf(0.f, v6));
            float na = sqrtf(fmaxf(0.f, v1)), nb = sqrtf(fmaxf(0.f, v3));
            float cosv = v4 / (fmaxf(na, 1e-8f) * fmaxf(nb, 1e-8f));
            float* o = g_stats + slice * 12;
            o[0] = mean_a; o[1] = std_a; o[2] = m7; o[3] = m8;
            o[4] = mean_b; o[5] = std_b; o[6] = m9; o[7] = m10;
            o[8] = mean_d; o[9] = std_d; o[10] = norm_d; o[11] = cosv;
        }
    }
}

// ============================================================================
// Kernel 2: tiny transformer. One block per batch element, 1024 threads.
// ============================================================================
#define QS 97  // qkv smem row stride (97 = conflict-free; 96 would be 32-way)

__global__ __launch_bounds__(1024) void k_transformer(
    const float* __restrict__ layer_emb,
    const float* __restrict__ in_proj_w, const float* __restrict__ in_proj_b,
    const float* __restrict__ ln1_g, const float* __restrict__ ln1_b,
    const float* __restrict__ qkv_w, const float* __restrict__ qkv_b,
    const float* __restrict__ out_w, const float* __restrict__ out_b,
    const float* __restrict__ ln2_g, const float* __restrict__ ln2_b,
    const float* __restrict__ ffn_w1, const float* __restrict__ ffn_b1,
    const float* __restrict__ ffn_w2, const float* __restrict__ ffn_b2,
    const float* __restrict__ gate_w, const float* __restrict__ gate_b,
    const float* __restrict__ row_w, const float* __restrict__ row_b,
    const float* __restrict__ col_w, const float* __restrict__ col_b,
    const float* __restrict__ drow_w, const float* __restrict__ drow_b,
    const float* __restrict__ dcol_w, const float* __restrict__ dcol_b,
    const float* __restrict__ delta_scale) {
    __shared__ float s_stats[64][12];
    __shared__ float s_feat[64][32];
    __shared__ float s_x[64][32];     // LN out, then attention out, then LN2 out
    __shared__ float s_h[64 * QS];    // qkv (stride 97), then FFN hidden (stride 64)

    const int bidx = blockIdx.x;
    const int t = threadIdx.x, lane = t & 31, wp = t >> 5;

    for (int o = t; o < 64 * 12; o += 1024)
        ((float*)s_stats)[o] = g_stats[bidx * 768 + o];
    __syncthreads();

    // in_proj + layer_emb
    for (int o = t; o < 2048; o += 1024) {
        int hp = o >> 5, d = o & 31;
        float acc = in_proj_b[d] + layer_emb[d];
#pragma unroll
        for (int s = 0; s < 12; s++) acc += s_stats[hp][s] * in_proj_w[d * 12 + s];
        s_feat[hp][d] = acc;
    }
    __syncthreads();

    // LN1 -> s_x
#pragma unroll
    for (int rep = 0; rep < 2; rep++) {
        int hp = wp + rep * 32;
        float v = s_feat[hp][lane];
        float mu = wredsum(v) * (1.f / 32.f);
        float df = v - mu;
        float var = wredsum(df * df) * (1.f / 32.f);
        s_x[hp][lane] = df * rsqrtf(var + 1e-5f) * ln1_g[lane] + ln1_b[lane];
    }
    __syncthreads();

    // qkv: s_h[hp*QS + j], j in [0,96)
    for (int o = t; o < 64 * 96; o += 1024) {
        int hp = o / 96, j = o % 96;
        float acc = qkv_b[j];
#pragma unroll
        for (int d = 0; d < 32; d++) acc += s_x[hp][d] * qkv_w[j * 32 + d];
        s_h[hp * QS + j] = acc;
    }
    __syncthreads();

    // attention: warp handles (h,q) pairs p = wp + 32c; lane covers keys {lane, lane+32}
#pragma unroll
    for (int c = 0; c < 4; c++) {
        int p = wp + c * 32;
        int h = p >> 6, q = p & 63;
        int qo = q * QS + h * 16;
        int ko = lane * QS + 32 + h * 16;
        int ko2 = (lane + 32) * QS + 32 + h * 16;
        float s0 = 0.f, s1 = 0.f;
#pragma unroll
        for (int dh = 0; dh < 16; dh++) {
            float qq = s_h[qo + dh];
            s0 += qq * s_h[ko + dh];
            s1 += qq * s_h[ko2 + dh];
        }
        s0 *= 0.25f; s1 *= 0.25f;
        float m = wredmax(fmaxf(s0, s1));
        float e0 = expf(s0 - m), e1 = expf(s1 - m);
        float inv = 1.f / wredsum(e0 + e1);
        int vo = lane * QS + 64 + h * 16;
        int vo2 = (lane + 32) * QS + 64 + h * 16;
#pragma unroll
        for (int dh = 0; dh < 16; dh++) {
            float part = e0 * s_h[vo + dh] + e1 * s_h[vo2 + dh];
            float sum = wredsum(part);
            if (lane == dh) s_x[q][h * 16 + dh] = sum * inv;
        }
    }
    __syncthreads();

    // out proj + residual
    for (int o = t; o < 2048; o += 1024) {
        int hp = o >> 5, d = o & 31;
        float acc = out_b[d];
#pragma unroll
        for (int e = 0; e < 32; e++) acc += s_x[hp][e] * out_w[d * 32 + e];
        s_feat[hp][d] += acc;
    }
    __syncthreads();

    // LN2 -> s_x
#pragma unroll
    for (int rep = 0; rep < 2; rep++) {
        int hp = wp + rep * 32;
        float v = s_feat[hp][lane];
        float mu = wredsum(v) * (1.f / 32.f);
        float df = v - mu;
        float var = wredsum(df * df) * (1.f / 32.f);
        s_x[hp][lane] = df * rsqrtf(var + 1e-5f) * ln2_g[lane] + ln2_b[lane];
    }
    __syncthreads();

    // FFN1 + exact GELU -> s_h[hp*64+f]
    for (int o = t; o < 64 * 64; o += 1024) {
        int hp = o >> 6, f = o & 63;
        float acc = ffn_b1[f];
#pragma unroll
        for (int d = 0; d < 32; d++) acc += s_x[hp][d] * ffn_w1[f * 32 + d];
        s_h[hp * 64 + f] = 0.5f * acc * (1.f + erff(acc * 0.70710678118654752f));
    }
    __syncthreads();

    // FFN2 + residual
    for (int o = t; o < 2048; o += 1024) {
        int hp = o >> 5, d = o & 31;
        float acc = ffn_b2[d];
#pragma unroll
        for (int f = 0; f < 64; f++) acc += s_h[hp * 64 + f] * ffn_w2[d * 64 + f];
        s_feat[hp][d] += acc;
    }
    __syncthreads();

    // output heads
    const float dscale = *delta_scale;
    const int base = bidx * 64;
    if (t < 64) {
        int hp = t;
        float acc = gate_b[0];
#pragma unroll
        for (int d = 0; d < 32; d++) acc += s_feat[hp][d] * gate_w[d];
        g_gate[base + hp] = acc;
    }
    for (int o = t; o < 64 * 256; o += 1024) {
        int hp = o >> 8, r = o & 255;
        int which = r >> 6, i = r & 63;
        const float* w; const float* bb; float* dst; float scale = 1.f;
        if (which == 0)      { w = row_w;  bb = row_b;  dst = g_row; }
        else if (which == 1) { w = col_w;  bb = col_b;  dst = g_col; }
        else if (which == 2) { w = drow_w; bb = drow_b; dst = g_drow; scale = dscale; }
        else                 { w = dcol_w; bb = dcol_b; dst = g_dcol; }
        float acc = bb[i];
#pragma unroll
        for (int d = 0; d < 32; d++) acc += s_feat[hp][d] * w[i * 32 + d];
        dst[(base + hp) * 64 + i] = acc * scale;
    }
}

// ============================================================================
// Kernel 3: merge. One block per (b,hp) slice, 256 threads x 16 elements.
// ============================================================================
__global__ __launch_bounds__(256) void k_merge(const float* __restrict__ a,
                                               const float* __restrict__ b,
                                               float* __restrict__ out) {
    const int slice = blockIdx.x;
    __shared__ float s_r[64], s_c[64], s_dr[64], s_dc[64];
    const int t = threadIdx.x;
    const int base = slice * 64;
    if (t < 64)        s_r[t] = g_gate[slice] + g_row[base + t];
    else if (t < 128)  s_c[t - 64] = g_col[base + t - 64];
    else if (t < 192)  s_dr[t - 128] = g_drow[base + t - 128];  // pre-scaled
    else               s_dc[t - 192] = g_dcol[base + t - 192];
    __syncthreads();

    const float4* a4 = (const float4*)a + slice * 1024;
    const float4* b4 = (const float4*)b + slice * 1024;
    float4* o4 = (float4*)out + slice * 1024;

    float4 va[4], vb[4];
#pragma unroll
    for (int k = 0; k < 4; k++) { va[k] = a4[t + k * 256]; vb[k] = b4[t + k * 256]; }
#pragma unroll
    for (int k = 0; k < 4; k++) {
        int p = t + k * 256;
        int i = p >> 4, jb = (p & 15) << 2;
        float g = s_r[i];
        float dr = s_dr[i];
        float4 r;
        {
            float m = 1.f / (1.f + expf(-(g + s_c[jb + 0])));
            r.x = vb[k].x + m * (va[k].x - vb[k].x) + dr * s_dc[jb + 0];
        }
        {
            float m = 1.f / (1.f + expf(-(g + s_c[jb + 1])));
            r.y = vb[k].y + m * (va[k].y - vb[k].y) + dr * s_dc[jb + 1];
        }
        {
            float m = 1.f / (1.f + expf(-(g + s_c[jb + 2])));
            r.z = vb[k].z + m * (va[k].z - vb[k].z) + dr * s_dc[jb + 2];
        }
        {
            float m = 1.f / (1.f + expf(-(g + s_c[jb + 3])));
            r.w = vb[k].w + m * (va[k].w - vb[k].w) + dr * s_dc[jb + 3];
        }
        o4[p] = r;
    }
}

// ============================================================================
extern "C" void kernel_launch(void* const* d_in, const int* in_sizes, int n_in,
                              void* d_out, int out_size) {
    const float* a = (const float*)d_in[0];
    const float* b = (const float*)d_in[1];

    k_stats<<<NBH, 256>>>(a, b);

    k_transformer<<<64, 1024>>>(
        (const float*)d_in[2],                          // layer_emb
        (const float*)d_in[3], (const float*)d_in[4],   // in_proj_w, in_proj_b
        (const float*)d_in[5], (const float*)d_in[6],   // ln1_g, ln1_b
        (const float*)d_in[7], (const float*)d_in[8],   // qkv_w, qkv_b
        (const float*)d_in[9], (const float*)d_in[10],  // out_w, out_b
        (const float*)d_in[11], (const float*)d_in[12], // ln2_g, ln2_b
        (const float*)d_in[13], (const float*)d_in[14], // ffn_w1, ffn_b1
        (const float*)d_in[15], (const float*)d_in[16], // ffn_w2, ffn_b2
        (const float*)d_in[17], (const float*)d_in[18], // gate_w, gate_b
        (const float*)d_in[19], (const float*)d_in[20], // row_w, row_b
        (const float*)d_in[21], (const float*)d_in[22], // col_w, col_b
        (const float*)d_in[23], (const float*)d_in[24], // drow_w, drow_b
        (const float*)d_in[25], (const float*)d_in[26], // dcol_w, dcol_b
        (const float*)d_in[27]);                        // delta_scale

    k_merge<<<NBH, 256>>>(a, b, (float*)d_out);
}

// round 3
// speedup vs baseline: 1.5720x; 1.5720x over previous
#include <cuda_runtime.h>
#include <math.h>

#define NPIX 4096   // H*W
#define NBH  4096   // B*HP

// Scratch (no allocation allowed -> __device__ globals)
__device__ float g_stats[NBH * 12];
__device__ float g_feat[NBH * 32];

__device__ __forceinline__ float wredsum(float v) {
#pragma unroll
    for (int o = 16; o; o >>= 1) v += __shfl_xor_sync(0xffffffffu, v, o);
    return v;
}
__device__ __forceinline__ float wredmax(float v) {
#pragma unroll
    for (int o = 16; o; o >>= 1) v = fmaxf(v, __shfl_xor_sync(0xffffffffu, v, o));
    return v;
}

// ============================================================================
// Kernel 1: per-(b,hp) statistics. One block per slice of 4096 elements.
// ============================================================================
__global__ __launch_bounds__(256) void k_stats(const float* __restrict__ a,
                                               const float* __restrict__ b) {
    const int slice = blockIdx.x;
    const float4* a4 = (const float4*)a + slice * (NPIX / 4);
    const float4* b4 = (const float4*)b + slice * (NPIX / 4);
    const int t = threadIdx.x;

    float sx = 0.f, sxx = 0.f, sy = 0.f, syy = 0.f, sxy = 0.f, sd = 0.f, sdd = 0.f;
    float mnx = INFINITY, mxx = -INFINITY, mny = INFINITY, mxy = -INFINITY;

    float4 va[4], vb[4];
#pragma unroll
    for (int k = 0; k < 4; k++) { va[k] = a4[t + k * 256]; vb[k] = b4[t + k * 256]; }
#pragma unroll
    for (int k = 0; k < 4; k++) {
        float xs[4] = {va[k].x, va[k].y, va[k].z, va[k].w};
        float ys[4] = {vb[k].x, vb[k].y, vb[k].z, vb[k].w};
#pragma unroll
        for (int e = 0; e < 4; e++) {
            float x = xs[e], y = ys[e];
            sx += x; sxx += x * x; sy += y; syy += y * y; sxy += x * y;
            float d = x - y; sd += d; sdd += d * d;
            mnx = fminf(mnx, x); mxx = fmaxf(mxx, x);
            mny = fminf(mny, y); mxy = fmaxf(mxy, y);
        }
    }

    sx = wredsum(sx); sxx = wredsum(sxx); sy = wredsum(sy); syy = wredsum(syy);
    sxy = wredsum(sxy); sd = wredsum(sd); sdd = wredsum(sdd);
    mnx = -wredmax(-mnx); mxx = wredmax(mxx);
    mny = -wredmax(-mny); mxy = wredmax(mxy);

    __shared__ float sh[8][11];
    const int wid = t >> 5, lane = t & 31;
    if (lane == 0) {
        float* r = sh[wid];
        r[0] = sx; r[1] = sxx; r[2] = sy; r[3] = syy; r[4] = sxy;
        r[5] = sd; r[6] = sdd; r[7] = mnx; r[8] = mxx; r[9] = mny; r[10] = mxy;
    }
    __syncthreads();
    if (t < 8) {
        float v0 = sh[t][0], v1 = sh[t][1], v2 = sh[t][2], v3 = sh[t][3], v4 = sh[t][4];
        float v5 = sh[t][5], v6 = sh[t][6];
        float m7 = sh[t][7], m8 = sh[t][8], m9 = sh[t][9], m10 = sh[t][10];
#pragma unroll
        for (int o = 4; o; o >>= 1) {
            v0 += __shfl_xor_sync(0xffu, v0, o);
            v1 += __shfl_xor_sync(0xffu, v1, o);
            v2 += __shfl_xor_sync(0xffu, v2, o);
            v3 += __shfl_xor_sync(0xffu, v3, o);
            v4 += __shfl_xor_sync(0xffu, v4, o);
            v5 += __shfl_xor_sync(0xffu, v5, o);
            v6 += __shfl_xor_sync(0xffu, v6, o);
            m7 = fminf(m7, __shfl_xor_sync(0xffu, m7, o));
            m8 = fmaxf(m8, __shfl_xor_sync(0xffu, m8, o));
            m9 = fminf(m9, __shfl_xor_sync(0xffu, m9, o));
            m10 = fmaxf(m10, __shfl_xor_sync(0xffu, m10, o));
        }
        if (t == 0) {
            const float N = 4096.f, NM1 = 4095.f;
            float mean_a = v0 / N;
            float std_a = sqrtf(fmaxf(0.f, (v1 - v0 * v0 / N) / NM1));
            float mean_b = v2 / N;
            float std_b = sqrtf(fmaxf(0.f, (v3 - v2 * v2 / N) / NM1));
            float mean_d = v5 / N;
            float std_d = sqrtf(fmaxf(0.f, (v6 - v5 * v5 / N) / NM1));
            float norm_d = sqrtf(fmaxf(0.f, v6));
            float na = sqrtf(fmaxf(0.f, v1)), nb = sqrtf(fmaxf(0.f, v3));
            float cosv = v4 / (fmaxf(na, 1e-8f) * fmaxf(nb, 1e-8f));
            float* o = g_stats + slice * 12;
            o[0] = mean_a; o[1] = std_a; o[2] = m7; o[3] = m8;
            o[4] = mean_b; o[5] = std_b; o[6] = m9; o[7] = m10;
            o[8] = mean_d; o[9] = std_d; o[10] = norm_d; o[11] = cosv;
        }
    }
}

// ============================================================================
// Kernel 2: transformer core (stats -> feat). One block per batch, 512 thr.
// ============================================================================
#define QS 97  // qkv smem row stride (97 = conflict-free; 96 would be 32-way)

__global__ __launch_bounds__(512) void k_transformer(
    const float* __restrict__ layer_emb,
    const float* __restrict__ in_proj_w, const float* __restrict__ in_proj_b,
    const float* __restrict__ ln1_g, const float* __restrict__ ln1_b,
    const float* __restrict__ qkv_w, const float* __restrict__ qkv_b,
    const float* __restrict__ out_w, const float* __restrict__ out_b,
    const float* __restrict__ ln2_g, const float* __restrict__ ln2_b,
    const float* __restrict__ ffn_w1, const float* __restrict__ ffn_b1,
    const float* __restrict__ ffn_w2, const float* __restrict__ ffn_b2) {
    __shared__ float s_stats[64][12];
    __shared__ float s_feat[64][32];
    __shared__ float s_x[64][32];     // LN out / attn out / LN2 out
    __shared__ float s_h[64 * QS];    // qkv (stride 97), then FFN hidden (stride 64)

    const int bidx = blockIdx.x;
    const int t = threadIdx.x, lane = t & 31, wp = t >> 5;  // wp in [0,16)

    for (int o = t; o < 64 * 12; o += 512)
        ((float*)s_stats)[o] = g_stats[bidx * 768 + o];
    __syncthreads();

    // in_proj + layer_emb
    for (int o = t; o < 2048; o += 512) {
        int hp = o >> 5, d = o & 31;
        float acc = in_proj_b[d] + layer_emb[d];
#pragma unroll
        for (int s = 0; s < 12; s++) acc += s_stats[hp][s] * in_proj_w[d * 12 + s];
        s_feat[hp][d] = acc;
    }
    __syncthreads();

    // LN1 -> s_x  (warp per hp row)
#pragma unroll
    for (int rep = 0; rep < 4; rep++) {
        int hp = rep * 16 + wp;
        float v = s_feat[hp][lane];
        float mu = wredsum(v) * (1.f / 32.f);
        float df = v - mu;
        float var = wredsum(df * df) * (1.f / 32.f);
        s_x[hp][lane] = df * rsqrtf(var + 1e-5f) * ln1_g[lane] + ln1_b[lane];
    }
    __syncthreads();

    // qkv: s_h[hp*QS + j], j in [0,96)
    for (int o = t; o < 64 * 96; o += 512) {
        int hp = o / 96, j = o % 96;
        float acc = qkv_b[j];
#pragma unroll
        for (int d = 0; d < 32; d++) acc += s_x[hp][d] * qkv_w[j * 32 + d];
        s_h[hp * QS + j] = acc;
    }
    __syncthreads();

    // attention: warp handles (h,q) pairs p; lane covers keys {lane, lane+32}
    for (int c = 0; c < 8; c++) {
        int p = c * 16 + wp;
        int h = p >> 6, q = p & 63;
        int qo = q * QS + h * 16;
        int ko = lane * QS + 32 + h * 16;
        int ko2 = (lane + 32) * QS + 32 + h * 16;
        float s0 = 0.f, s1 = 0.f;
#pragma unroll
        for (int dh = 0; dh < 16; dh++) {
            float qq = s_h[qo + dh];
            s0 += qq * s_h[ko + dh];
            s1 += qq * s_h[ko2 + dh];
        }
        s0 *= 0.25f; s1 *= 0.25f;
        float m = wredmax(fmaxf(s0, s1));
        float e0 = expf(s0 - m), e1 = expf(s1 - m);
        float inv = 1.f / wredsum(e0 + e1);
        int vo = lane * QS + 64 + h * 16;
        int vo2 = (lane + 32) * QS + 64 + h * 16;
#pragma unroll
        for (int dh = 0; dh < 16; dh++) {
            float part = e0 * s_h[vo + dh] + e1 * s_h[vo2 + dh];
            float sum = wredsum(part);
            if (lane == dh) s_x[q][h * 16 + dh] = sum * inv;
        }
    }
    __syncthreads();

    // out proj + residual
    for (int o = t; o < 2048; o += 512) {
        int hp = o >> 5, d = o & 31;
        float acc = out_b[d];
#pragma unroll
        for (int e = 0; e < 32; e++) acc += s_x[hp][e] * out_w[d * 32 + e];
        s_feat[hp][d] += acc;
    }
    __syncthreads();

    // LN2 -> s_x
#pragma unroll
    for (int rep = 0; rep < 4; rep++) {
        int hp = rep * 16 + wp;
        float v = s_feat[hp][lane];
        float mu = wredsum(v) * (1.f / 32.f);
        float df = v - mu;
        float var = wredsum(df * df) * (1.f / 32.f);
        s_x[hp][lane] = df * rsqrtf(var + 1e-5f) * ln2_g[lane] + ln2_b[lane];
    }
    __syncthreads();

    // FFN1 + exact GELU -> s_h[hp*64+f]
    for (int o = t; o < 64 * 64; o += 512) {
        int hp = o >> 6, f = o & 63;
        float acc = ffn_b1[f];
#pragma unroll
        for (int d = 0; d < 32; d++) acc += s_x[hp][d] * ffn_w1[f * 32 + d];
        s_h[hp * 64 + f] = 0.5f * acc * (1.f + erff(acc * 0.70710678118654752f));
    }
    __syncthreads();

    // FFN2 + residual, write feat to global
    for (int o = t; o < 2048; o += 512) {
        int hp = o >> 5, d = o & 31;
        float acc = ffn_b2[d];
#pragma unroll
        for (int f = 0; f < 64; f++) acc += s_h[hp * 64 + f] * ffn_w2[d * 64 + f];
        g_feat[bidx * 2048 + o] = s_feat[hp][d] + acc;
    }
}

// ============================================================================
// Kernel 3: heads + merge. One block per (b,hp) slice, 256 threads.
// ============================================================================
__global__ __launch_bounds__(256) void k_merge(
    const float* __restrict__ a, const float* __restrict__ b,
    float* __restrict__ out,
    const float* __restrict__ gate_w, const float* __restrict__ gate_b,
    const float* __restrict__ row_w, const float* __restrict__ row_b,
    const float* __restrict__ col_w, const float* __restrict__ col_b,
    const float* __restrict__ drow_w, const float* __restrict__ drow_b,
    const float* __restrict__ dcol_w, const float* __restrict__ dcol_b,
    const float* __restrict__ delta_scale) {
    const int slice = blockIdx.x;
    const int t = threadIdx.x;

    __shared__ float s_feat[32];
    __shared__ float s_r[64], s_c[64], s_dr[64], s_dc[64];
    __shared__ float s_gate;

    if (t < 32) s_feat[t] = g_feat[slice * 32 + t];
    __syncthreads();

    // 256 threads -> 4 head groups x 64 outputs; thread 0 also does gate
    {
        int which = t >> 6, i = t & 63;
        const float* w; const float* bb; float* dst;
        if (which == 0)      { w = row_w;  bb = row_b;  dst = s_r; }
        else if (which == 1) { w = col_w;  bb = col_b;  dst = s_c; }
        else if (which == 2) { w = drow_w; bb = drow_b; dst = s_dr; }
        else                 { w = dcol_w; bb = dcol_b; dst = s_dc; }
        float acc = bb[i];
#pragma unroll
        for (int d = 0; d < 32; d++) acc += s_feat[d] * w[i * 32 + d];
        if (which == 2) acc *= *delta_scale;  // pre-scale drow by delta_scale
        dst[i] = acc;
        if (t == 0) {
            float g = gate_b[0];
#pragma unroll
            for (int d = 0; d < 32; d++) g += s_feat[d] * gate_w[d];
            s_gate = g;
        }
    }
    __syncthreads();

    const float4* a4 = (const float4*)a + slice * 1024;
    const float4* b4 = (const float4*)b + slice * 1024;
    float4* o4 = (float4*)out + slice * 1024;
    const float gate = s_gate;

    float4 va[4], vb[4];
#pragma unroll
    for (int k = 0; k < 4; k++) { va[k] = a4[t + k * 256]; vb[k] = b4[t + k * 256]; }
#pragma unroll
    for (int k = 0; k < 4; k++) {
        int p = t + k * 256;
        int i = p >> 4, jb = (p & 15) << 2;
        float g = gate + s_r[i];
        float dr = s_dr[i];
        float4 r;
        {
            float m = 1.f / (1.f + expf(-(g + s_c[jb + 0])));
            r.x = vb[k].x + m * (va[k].x - vb[k].x) + dr * s_dc[jb + 0];
        }
        {
            float m = 1.f / (1.f + expf(-(g + s_c[jb + 1])));
            r.y = vb[k].y + m * (va[k].y - vb[k].y) + dr * s_dc[jb + 1];
        }
        {
            float m = 1.f / (1.f + expf(-(g + s_c[jb + 2])));
            r.z = vb[k].z + m * (va[k].z - vb[k].z) + dr * s_dc[jb + 2];
        }
        {
            float m = 1.f / (1.f + expf(-(g + s_c[jb + 3])));
            r.w = vb[k].w + m * (va[k].w - vb[k].w) + dr * s_dc[jb + 3];
        }
        o4[p] = r;
    }
}

// ============================================================================
extern "C" void kernel_launch(void* const* d_in, const int* in_sizes, int n_in,
                              void* d_out, int out_size) {
    const float* a = (const float*)d_in[0];
    const float* b = (const float*)d_in[1];

    k_stats<<<NBH, 256>>>(a, b);

    k_transformer<<<64, 512>>>(
        (const float*)d_in[2],                          // layer_emb
        (const float*)d_in[3], (const float*)d_in[4],   // in_proj_w, in_proj_b
        (const float*)d_in[5], (const float*)d_in[6],   // ln1_g, ln1_b
        (const float*)d_in[7], (const float*)d_in[8],   // qkv_w, qkv_b
        (const float*)d_in[9], (const float*)d_in[10],  // out_w, out_b
        (const float*)d_in[11], (const float*)d_in[12], // ln2_g, ln2_b
        (const float*)d_in[13], (const float*)d_in[14], // ffn_w1, ffn_b1
        (const float*)d_in[15], (const float*)d_in[16]);// ffn_w2, ffn_b2

    k_merge<<<NBH, 256>>>(
        a, b, (float*)d_out,
        (const float*)d_in[17], (const float*)d_in[18], // gate_w, gate_b
        (const float*)d_in[19], (const float*)d_in[20], // row_w, row_b
        (const float*)d_in[21], (const float*)d_in[22], // col_w, col_b
        (const float*)d_in[23], (const float*)d_in[24], // drow_w, drow_b
        (const float*)d_in[25], (const float*)d_in[26], // dcol_w, dcol_b
        (const float*)d_in[27]);                        // delta_scale
}

// round 4
// speedup vs baseline: 2.3036x; 1.4654x over previous
#include <cuda_runtime.h>
#include <math.h>

#define NPIX 4096   // H*W
#define NBH  4096   // B*HP

// Scratch (no allocation allowed -> __device__ globals)
__device__ float g_stats[NBH * 12];
__device__ float g_feat[NBH * 32];

__device__ __forceinline__ float wredsum(float v) {
#pragma unroll
    for (int o = 16; o; o >>= 1) v += __shfl_xor_sync(0xffffffffu, v, o);
    return v;
}
__device__ __forceinline__ float wredmax(float v) {
#pragma unroll
    for (int o = 16; o; o >>= 1) v = fmaxf(v, __shfl_xor_sync(0xffffffffu, v, o));
    return v;
}

// FMA-only sigmoid: no MUFU. exp2 via round-trick + deg-5 Taylor, recip via
// bit-hack + 3 Newton steps. abs err < ~1e-6.
__device__ __forceinline__ float fsig(float x) {
    x = fmaxf(-18.f, fminf(18.f, x));
    float z = x * -1.4426950408889634f;          // -x * log2(e); e^-x = 2^z
    float fz = z + 12582912.0f;                  // round-to-nearest-int trick
    int iz = __float_as_int(fz) - 0x4B400000;    // round(z)
    float zf = z - (float)iz;                    // in [-0.5, 0.5]
    float p = 0.00133335581f;
    p = fmaf(p, zf, 0.00961812911f);
    p = fmaf(p, zf, 0.05550410866f);
    p = fmaf(p, zf, 0.24022650700f);
    p = fmaf(p, zf, 0.69314718056f);
    p = fmaf(p, zf, 1.0f);
    float scale = __int_as_float((iz + 127) << 23);
    float y = fmaf(p, scale, 1.0f);              // 1 + e^-x  (>= 1)
    float r = __int_as_float(0x7EF311C3 - __float_as_int(y));
    r = r * (2.0f - y * r);
    r = r * (2.0f - y * r);
    r = r * (2.0f - y * r);
    return r;
}

// ============================================================================
// Kernel 1: per-(b,hp) statistics. One block per slice of 4096 elements.
// ============================================================================
__global__ __launch_bounds__(256) void k_stats(const float* __restrict__ a,
                                               const float* __restrict__ b) {
    const int slice = blockIdx.x;
    const float4* a4 = (const float4*)a + slice * (NPIX / 4);
    const float4* b4 = (const float4*)b + slice * (NPIX / 4);
    const int t = threadIdx.x;

    float sx = 0.f, sxx = 0.f, sy = 0.f, syy = 0.f, sxy = 0.f, sd = 0.f, sdd = 0.f;
    float mnx = INFINITY, mxx = -INFINITY, mny = INFINITY, mxy = -INFINITY;

    float4 va[4], vb[4];
#pragma unroll
    for (int k = 0; k < 4; k++) { va[k] = a4[t + k * 256]; vb[k] = b4[t + k * 256]; }
#pragma unroll
    for (int k = 0; k < 4; k++) {
        float xs[4] = {va[k].x, va[k].y, va[k].z, va[k].w};
        float ys[4] = {vb[k].x, vb[k].y, vb[k].z, vb[k].w};
#pragma unroll
        for (int e = 0; e < 4; e++) {
            float x = xs[e], y = ys[e];
            sx += x; sxx += x * x; sy += y; syy += y * y; sxy += x * y;
            float d = x - y; sd += d; sdd += d * d;
            mnx = fminf(mnx, x); mxx = fmaxf(mxx, x);
            mny = fminf(mny, y); mxy = fmaxf(mxy, y);
        }
    }

    sx = wredsum(sx); sxx = wredsum(sxx); sy = wredsum(sy); syy = wredsum(syy);
    sxy = wredsum(sxy); sd = wredsum(sd); sdd = wredsum(sdd);
    mnx = -wredmax(-mnx); mxx = wredmax(mxx);
    mny = -wredmax(-mny); mxy = wredmax(mxy);

    __shared__ float sh[8][11];
    const int wid = t >> 5, lane = t & 31;
    if (lane == 0) {
        float* r = sh[wid];
        r[0] = sx; r[1] = sxx; r[2] = sy; r[3] = syy; r[4] = sxy;
        r[5] = sd; r[6] = sdd; r[7] = mnx; r[8] = mxx; r[9] = mny; r[10] = mxy;
    }
    __syncthreads();
    if (t < 8) {
        float v0 = sh[t][0], v1 = sh[t][1], v2 = sh[t][2], v3 = sh[t][3], v4 = sh[t][4];
        float v5 = sh[t][5], v6 = sh[t][6];
        float m7 = sh[t][7], m8 = sh[t][8], m9 = sh[t][9], m10 = sh[t][10];
#pragma unroll
        for (int o = 4; o; o >>= 1) {
            v0 += __shfl_xor_sync(0xffu, v0, o);
            v1 += __shfl_xor_sync(0xffu, v1, o);
            v2 += __shfl_xor_sync(0xffu, v2, o);
            v3 += __shfl_xor_sync(0xffu, v3, o);
            v4 += __shfl_xor_sync(0xffu, v4, o);
            v5 += __shfl_xor_sync(0xffu, v5, o);
            v6 += __shfl_xor_sync(0xffu, v6, o);
            m7 = fminf(m7, __shfl_xor_sync(0xffu, m7, o));
            m8 = fmaxf(m8, __shfl_xor_sync(0xffu, m8, o));
            m9 = fminf(m9, __shfl_xor_sync(0xffu, m9, o));
            m10 = fmaxf(m10, __shfl_xor_sync(0xffu, m10, o));
        }
        if (t == 0) {
            const float N = 4096.f, NM1 = 4095.f;
            float mean_a = v0 / N;
            float std_a = sqrtf(fmaxf(0.f, (v1 - v0 * v0 / N) / NM1));
            float mean_b = v2 / N;
            float std_b = sqrtf(fmaxf(0.f, (v3 - v2 * v2 / N) / NM1));
            float mean_d = v5 / N;
            float std_d = sqrtf(fmaxf(0.f, (v6 - v5 * v5 / N) / NM1));
            float norm_d = sqrtf(fmaxf(0.f, v6));
            float na = sqrtf(fmaxf(0.f, v1)), nb = sqrtf(fmaxf(0.f, v3));
            float cosv = v4 / (fmaxf(na, 1e-8f) * fmaxf(nb, 1e-8f));
            float* o = g_stats + slice * 12;
            o[0] = mean_a; o[1] = std_a; o[2] = m7; o[3] = m8;
            o[4] = mean_b; o[5] = std_b; o[6] = m9; o[7] = m10;
            o[8] = mean_d; o[9] = std_d; o[10] = norm_d; o[11] = cosv;
        }
    }
}

// ============================================================================
// Kernel 2: transformer core (stats -> feat). One block per batch, 512 thr.
// ============================================================================
#define QS 97  // qkv smem row stride (97 = conflict-free; 96 would be 32-way)

__global__ __launch_bounds__(512) void k_transformer(
    const float* __restrict__ layer_emb,
    const float* __restrict__ in_proj_w, const float* __restrict__ in_proj_b,
    const float* __restrict__ ln1_g, const float* __restrict__ ln1_b,
    const float* __restrict__ qkv_w, const float* __restrict__ qkv_b,
    const float* __restrict__ out_w, const float* __restrict__ out_b,
    const float* __restrict__ ln2_g, const float* __restrict__ ln2_b,
    const float* __restrict__ ffn_w1, const float* __restrict__ ffn_b1,
    const float* __restrict__ ffn_w2, const float* __restrict__ ffn_b2) {
    __shared__ float s_stats[64][12];
    __shared__ float s_feat[64][32];
    __shared__ float s_x[64][32];     // LN out / attn out / LN2 out
    __shared__ float s_h[64 * QS];    // qkv (stride 97), then FFN hidden (stride 64)

    const int bidx = blockIdx.x;
    const int t = threadIdx.x, lane = t & 31, wp = t >> 5;  // wp in [0,16)

    for (int o = t; o < 64 * 12; o += 512)
        ((float*)s_stats)[o] = g_stats[bidx * 768 + o];
    __syncthreads();

    // in_proj + layer_emb
    for (int o = t; o < 2048; o += 512) {
        int hp = o >> 5, d = o & 31;
        float acc = in_proj_b[d] + layer_emb[d];
#pragma unroll
        for (int s = 0; s < 12; s++) acc += s_stats[hp][s] * in_proj_w[d * 12 + s];
        s_feat[hp][d] = acc;
    }
    __syncthreads();

    // LN1 -> s_x  (warp per hp row)
#pragma unroll
    for (int rep = 0; rep < 4; rep++) {
        int hp = rep * 16 + wp;
        float v = s_feat[hp][lane];
        float mu = wredsum(v) * (1.f / 32.f);
        float df = v - mu;
        float var = wredsum(df * df) * (1.f / 32.f);
        s_x[hp][lane] = df * rsqrtf(var + 1e-5f) * ln1_g[lane] + ln1_b[lane];
    }
    __syncthreads();

    // qkv: s_h[hp*QS + j], j in [0,96)
    for (int o = t; o < 64 * 96; o += 512) {
        int hp = o / 96, j = o % 96;
        float acc = qkv_b[j];
#pragma unroll
        for (int d = 0; d < 32; d++) acc += s_x[hp][d] * qkv_w[j * 32 + d];
        s_h[hp * QS + j] = acc;
    }
    __syncthreads();

    // attention: warp handles (h,q) pairs p; lane covers keys {lane, lane+32}
    for (int c = 0; c < 8; c++) {
        int p = c * 16 + wp;
        int h = p >> 6, q = p & 63;
        int qo = q * QS + h * 16;
        int ko = lane * QS + 32 + h * 16;
        int ko2 = (lane + 32) * QS + 32 + h * 16;
        float s0 = 0.f, s1 = 0.f;
#pragma unroll
        for (int dh = 0; dh < 16; dh++) {
            float qq = s_h[qo + dh];
            s0 += qq * s_h[ko + dh];
            s1 += qq * s_h[ko2 + dh];
        }
        s0 *= 0.25f; s1 *= 0.25f;
        float m = wredmax(fmaxf(s0, s1));
        float e0 = expf(s0 - m), e1 = expf(s1 - m);
        float inv = 1.f / wredsum(e0 + e1);
        int vo = lane * QS + 64 + h * 16;
        int vo2 = (lane + 32) * QS + 64 + h * 16;
#pragma unroll
        for (int dh = 0; dh < 16; dh++) {
            float part = e0 * s_h[vo + dh] + e1 * s_h[vo2 + dh];
            float sum = wredsum(part);
            if (lane == dh) s_x[q][h * 16 + dh] = sum * inv;
        }
    }
    __syncthreads();

    // out proj + residual
    for (int o = t; o < 2048; o += 512) {
        int hp = o >> 5, d = o & 31;
        float acc = out_b[d];
#pragma unroll
        for (int e = 0; e < 32; e++) acc += s_x[hp][e] * out_w[d * 32 + e];
        s_feat[hp][d] += acc;
    }
    __syncthreads();

    // LN2 -> s_x
#pragma unroll
    for (int rep = 0; rep < 4; rep++) {
        int hp = rep * 16 + wp;
        float v = s_feat[hp][lane];
        float mu = wredsum(v) * (1.f / 32.f);
        float df = v - mu;
        float var = wredsum(df * df) * (1.f / 32.f);
        s_x[hp][lane] = df * rsqrtf(var + 1e-5f) * ln2_g[lane] + ln2_b[lane];
    }
    __syncthreads();

    // FFN1 + exact GELU -> s_h[hp*64+f]
    for (int o = t; o < 64 * 64; o += 512) {
        int hp = o >> 6, f = o & 63;
        float acc = ffn_b1[f];
#pragma unroll
        for (int d = 0; d < 32; d++) acc += s_x[hp][d] * ffn_w1[f * 32 + d];
        s_h[hp * 64 + f] = 0.5f * acc * (1.f + erff(acc * 0.70710678118654752f));
    }
    __syncthreads();

    // FFN2 + residual, write feat to global
    for (int o = t; o < 2048; o += 512) {
        int hp = o >> 5, d = o & 31;
        float acc = ffn_b2[d];
#pragma unroll
        for (int f = 0; f < 64; f++) acc += s_h[hp * 64 + f] * ffn_w2[d * 64 + f];
        g_feat[bidx * 2048 + o] = s_feat[hp][d] + acc;
    }
}

// ============================================================================
// Kernel 3: heads + merge. One block per (b,hp) slice, 256 threads.
// Heads: coalesced float4 weight loads, 8-lane partial reductions.
// Merge: FMA-only sigmoid (no MUFU).
// ============================================================================
__global__ __launch_bounds__(256) void k_merge(
    const float* __restrict__ a, const float* __restrict__ b,
    float* __restrict__ out,
    const float* __restrict__ gate_w, const float* __restrict__ gate_b,
    const float* __restrict__ row_w, const float* __restrict__ row_b,
    const float* __restrict__ col_w, const float* __restrict__ col_b,
    const float* __restrict__ drow_w, const float* __restrict__ drow_b,
    const float* __restrict__ dcol_w, const float* __restrict__ dcol_b,
    const float* __restrict__ delta_scale) {
    const int slice = blockIdx.x;
    const int t = threadIdx.x, lane = t & 31, wp = t >> 5;

    __shared__ float s_feat[32];
    __shared__ float s_r[64], s_c[64], s_dr[64], s_dc[64];
    __shared__ float s_gate;

    if (t < 32) s_feat[t] = g_feat[slice * 32 + t];
    __syncthreads();

    // Heads: 8 warps. warp wp -> matrix (wp>>1), half (wp&1) of 64 outputs.
    // Per group of 4 outputs: 8 lanes each, lane loads float4 of weights
    // (fully coalesced), 4 FMA, 3-shuffle reduce within the 8-lane group.
    {
        const int mat = wp >> 1;
        const float* w; const float* bb; float* dst;
        if (mat == 0)      { w = row_w;  bb = row_b;  dst = s_r; }
        else if (mat == 1) { w = col_w;  bb = col_b;  dst = s_c; }
        else if (mat == 2) { w = drow_w; bb = drow_b; dst = s_dr; }
        else               { w = dcol_w; bb = dcol_b; dst = s_dc; }
        const int g = lane >> 3;      // output within group of 4
        const int dsub = lane & 7;    // which float4 of the 8 per row
        float4 f4 = ((const float4*)s_feat)[dsub];
        const float dscale = (mat == 2) ? *delta_scale : 1.f;
#pragma unroll
        for (int ii = 0; ii < 8; ii++) {
            int i = (wp & 1) * 32 + ii * 4 + g;
            float4 w4 = ((const float4*)w)[i * 8 + dsub];
            float v = w4.x * f4.x + w4.y * f4.y + w4.z * f4.z + w4.w * f4.w;
            v += __shfl_xor_sync(0xffffffffu, v, 1);
            v += __shfl_xor_sync(0xffffffffu, v, 2);
            v += __shfl_xor_sync(0xffffffffu, v, 4);
            if (dsub == 0) dst[i] = (v + bb[i]) * dscale;
        }
        if (wp == 0) {
            float gv = s_feat[lane] * gate_w[lane];
            gv = wredsum(gv);
            if (lane == 0) s_gate = gv + gate_b[0];
        }
    }
    __syncthreads();

    const float4* a4 = (const float4*)a + slice * 1024;
    const float4* b4 = (const float4*)b + slice * 1024;
    float4* o4 = (float4*)out + slice * 1024;
    const float gate = s_gate;

    float4 va[4], vb[4];
#pragma unroll
    for (int k = 0; k < 4; k++) { va[k] = a4[t + k * 256]; vb[k] = b4[t + k * 256]; }
#pragma unroll
    for (int k = 0; k < 4; k++) {
        int p = t + k * 256;
        int i = p >> 4, jb = (p & 15) << 2;
        float g = gate + s_r[i];
        float dr = s_dr[i];   // pre-scaled by delta_scale
        float4 c4 = ((const float4*)s_c)[p & 15];
        float4 dc4 = ((const float4*)s_dc)[p & 15];
        float4 r;
        {
            float m = fsig(g + c4.x);
            r.x = vb[k].x + m * (va[k].x - vb[k].x) + dr * dc4.x;
        }
        {
            float m = fsig(g + c4.y);
            r.y = vb[k].y + m * (va[k].y - vb[k].y) + dr * dc4.y;
        }
        {
            float m = fsig(g + c4.z);
            r.z = vb[k].z + m * (va[k].z - vb[k].z) + dr * dc4.z;
        }
        {
            float m = fsig(g + c4.w);
            r.w = vb[k].w + m * (va[k].w - vb[k].w) + dr * dc4.w;
        }
        o4[p] = r;
    }
}

// ============================================================================
extern "C" void kernel_launch(void* const* d_in, const int* in_sizes, int n_in,
                              void* d_out, int out_size) {
    const float* a = (const float*)d_in[0];
    const float* b = (const float*)d_in[1];

    k_stats<<<NBH, 256>>>(a, b);

    k_transformer<<<64, 512>>>(
        (const float*)d_in[2],                          // layer_emb
        (const float*)d_in[3], (const float*)d_in[4],   // in_proj_w, in_proj_b
        (const float*)d_in[5], (const float*)d_in[6],   // ln1_g, ln1_b
        (const float*)d_in[7], (const float*)d_in[8],   // qkv_w, qkv_b
        (const float*)d_in[9], (const float*)d_in[10],  // out_w, out_b
        (const float*)d_in[11], (const float*)d_in[12], // ln2_g, ln2_b
        (const float*)d_in[13], (const float*)d_in[14], // ffn_w1, ffn_b1
        (const float*)d_in[15], (const float*)d_in[16]);// ffn_w2, ffn_b2

    k_merge<<<NBH, 256>>>(
        a, b, (float*)d_out,
        (const float*)d_in[17], (const float*)d_in[18], // gate_w, gate_b
        (const float*)d_in[19], (const float*)d_in[20], // row_w, row_b
        (const float*)d_in[21], (const float*)d_in[22], // col_w, col_b
        (const float*)d_in[23], (const float*)d_in[24], // drow_w, drow_b
        (const float*)d_in[25], (const float*)d_in[26], // dcol_w, dcol_b
        (const float*)d_in[27]);                        // delta_scale
}

// round 5
// speedup vs baseline: 5.1584x; 2.2393x over previous
#include <cuda_runtime.h>
#include <math.h>

#define NPIX 4096   // H*W
#define NBH  4096   // B*HP

// Scratch (no allocation allowed -> __device__ globals)
__device__ float g_stats[NBH * 12];
__device__ float g_feat[NBH * 32];

__device__ __forceinline__ float wredsum(float v) {
#pragma unroll
    for (int o = 16; o; o >>= 1) v += __shfl_xor_sync(0xffffffffu, v, o);
    return v;
}
__device__ __forceinline__ float wredmax(float v) {
#pragma unroll
    for (int o = 16; o; o >>= 1) v = fmaxf(v, __shfl_xor_sync(0xffffffffu, v, o));
    return v;
}

// FMA-only sigmoid: no MUFU. exp2 via round-trick + deg-5 Taylor, recip via
// bit-hack + 3 Newton steps. abs err < ~1e-6.
__device__ __forceinline__ float fsig(float x) {
    x = fmaxf(-18.f, fminf(18.f, x));
    float z = x * -1.4426950408889634f;
    float fz = z + 12582912.0f;
    int iz = __float_as_int(fz) - 0x4B400000;
    float zf = z - (float)iz;
    float p = 0.00133335581f;
    p = fmaf(p, zf, 0.00961812911f);
    p = fmaf(p, zf, 0.05550410866f);
    p = fmaf(p, zf, 0.24022650700f);
    p = fmaf(p, zf, 0.69314718056f);
    p = fmaf(p, zf, 1.0f);
    float scale = __int_as_float((iz + 127) << 23);
    float y = fmaf(p, scale, 1.0f);              // 1 + e^-x
    float r = __int_as_float(0x7EF311C3 - __float_as_int(y));
    r = r * (2.0f - y * r);
    r = r * (2.0f - y * r);
    r = r * (2.0f - y * r);
    return r;
}

// ============================================================================
// Kernel 1: per-(b,hp) statistics. One block per slice of 4096 elements.
// ============================================================================
__global__ __launch_bounds__(256) void k_stats(const float* __restrict__ a,
                                               const float* __restrict__ b) {
    const int slice = blockIdx.x;
    const float4* a4 = (const float4*)a + slice * (NPIX / 4);
    const float4* b4 = (const float4*)b + slice * (NPIX / 4);
    const int t = threadIdx.x;

    float sx = 0.f, sxx = 0.f, sy = 0.f, syy = 0.f, sxy = 0.f, sd = 0.f, sdd = 0.f;
    float mnx = INFINITY, mxx = -INFINITY, mny = INFINITY, mxy = -INFINITY;

    float4 va[4], vb[4];
#pragma unroll
    for (int k = 0; k < 4; k++) { va[k] = a4[t + k * 256]; vb[k] = b4[t + k * 256]; }
#pragma unroll
    for (int k = 0; k < 4; k++) {
        float xs[4] = {va[k].x, va[k].y, va[k].z, va[k].w};
        float ys[4] = {vb[k].x, vb[k].y, vb[k].z, vb[k].w};
#pragma unroll
        for (int e = 0; e < 4; e++) {
            float x = xs[e], y = ys[e];
            sx += x; sxx += x * x; sy += y; syy += y * y; sxy += x * y;
            float d = x - y; sd += d; sdd += d * d;
            mnx = fminf(mnx, x); mxx = fmaxf(mxx, x);
            mny = fminf(mny, y); mxy = fmaxf(mxy, y);
        }
    }

    sx = wredsum(sx); sxx = wredsum(sxx); sy = wredsum(sy); syy = wredsum(syy);
    sxy = wredsum(sxy); sd = wredsum(sd); sdd = wredsum(sdd);
    mnx = -wredmax(-mnx); mxx = wredmax(mxx);
    mny = -wredmax(-mny); mxy = wredmax(mxy);

    __shared__ float sh[8][11];
    const int wid = t >> 5, lane = t & 31;
    if (lane == 0) {
        float* r = sh[wid];
        r[0] = sx; r[1] = sxx; r[2] = sy; r[3] = syy; r[4] = sxy;
        r[5] = sd; r[6] = sdd; r[7] = mnx; r[8] = mxx; r[9] = mny; r[10] = mxy;
    }
    __syncthreads();
    if (t < 8) {
        float v0 = sh[t][0], v1 = sh[t][1], v2 = sh[t][2], v3 = sh[t][3], v4 = sh[t][4];
        float v5 = sh[t][5], v6 = sh[t][6];
        float m7 = sh[t][7], m8 = sh[t][8], m9 = sh[t][9], m10 = sh[t][10];
#pragma unroll
        for (int o = 4; o; o >>= 1) {
            v0 += __shfl_xor_sync(0xffu, v0, o);
            v1 += __shfl_xor_sync(0xffu, v1, o);
            v2 += __shfl_xor_sync(0xffu, v2, o);
            v3 += __shfl_xor_sync(0xffu, v3, o);
            v4 += __shfl_xor_sync(0xffu, v4, o);
            v5 += __shfl_xor_sync(0xffu, v5, o);
            v6 += __shfl_xor_sync(0xffu, v6, o);
            m7 = fminf(m7, __shfl_xor_sync(0xffu, m7, o));
            m8 = fmaxf(m8, __shfl_xor_sync(0xffu, m8, o));
            m9 = fminf(m9, __shfl_xor_sync(0xffu, m9, o));
            m10 = fmaxf(m10, __shfl_xor_sync(0xffu, m10, o));
        }
        if (t == 0) {
            const float N = 4096.f, NM1 = 4095.f;
            float mean_a = v0 / N;
            float std_a = sqrtf(fmaxf(0.f, (v1 - v0 * v0 / N) / NM1));
            float mean_b = v2 / N;
            float std_b = sqrtf(fmaxf(0.f, (v3 - v2 * v2 / N) / NM1));
            float mean_d = v5 / N;
            float std_d = sqrtf(fmaxf(0.f, (v6 - v5 * v5 / N) / NM1));
            float norm_d = sqrtf(fmaxf(0.f, v6));
            float na = sqrtf(fmaxf(0.f, v1)), nb = sqrtf(fmaxf(0.f, v3));
            float cosv = v4 / (fmaxf(na, 1e-8f) * fmaxf(nb, 1e-8f));
            float* o = g_stats + slice * 12;
            o[0] = mean_a; o[1] = std_a; o[2] = m7; o[3] = m8;
            o[4] = mean_b; o[5] = std_b; o[6] = m9; o[7] = m10;
            o[8] = mean_d; o[9] = std_d; o[10] = norm_d; o[11] = cosv;
        }
    }
}

// ============================================================================
// Kernel 2: transformer core. One block per batch, 512 threads.
// ALL weight matrices staged via smem (coalesced GMEM, padded banks).
// ============================================================================
__global__ __launch_bounds__(512) void k_transformer(
    const float* __restrict__ layer_emb,
    const float* __restrict__ in_proj_w, const float* __restrict__ in_proj_b,
    const float* __restrict__ ln1_g, const float* __restrict__ ln1_b,
    const float* __restrict__ qkv_w, const float* __restrict__ qkv_b,
    const float* __restrict__ out_w, const float* __restrict__ out_b,
    const float* __restrict__ ln2_g, const float* __restrict__ ln2_b,
    const float* __restrict__ ffn_w1, const float* __restrict__ ffn_b1,
    const float* __restrict__ ffn_w2, const float* __restrict__ ffn_b2) {
    __shared__ float s_stats[64][12];
    __shared__ float s_feat[64][32];
    __shared__ float s_x[64][32];     // LN1 out -> q -> attn out -> LN2 out
    __shared__ float s_kv[64 * 65];   // k (cols 0..31), v (cols 32..63); then FFN hidden (stride 64)
    __shared__ float s_w[2112];       // weight staging (max: ffn_w1 64x33)

    const int bidx = blockIdx.x;
    const int t = threadIdx.x, lane = t & 31, wp = t >> 5;  // wp in [0,16)

    // stage stats + in_proj_w (pad stride 13)
    for (int o = t; o < 64 * 12; o += 512)
        ((float*)s_stats)[o] = g_stats[bidx * 768 + o];
    for (int o = t; o < 32 * 12; o += 512)
        s_w[(o / 12) * 13 + (o % 12)] = in_proj_w[o];
    __syncthreads();

    // in_proj + layer_emb
    for (int o = t; o < 2048; o += 512) {
        int hp = o >> 5, d = o & 31;
        float acc = in_proj_b[d] + layer_emb[d];
#pragma unroll
        for (int s = 0; s < 12; s++) acc += s_stats[hp][s] * s_w[d * 13 + s];
        s_feat[hp][d] = acc;
    }
    __syncthreads();

    // LN1 -> s_x (warp per hp row)
#pragma unroll
    for (int rep = 0; rep < 4; rep++) {
        int hp = rep * 16 + wp;
        float v = s_feat[hp][lane];
        float mu = wredsum(v) * (1.f / 32.f);
        float df = v - mu;
        float var = wredsum(df * df) * (1.f / 32.f);
        s_x[hp][lane] = df * rsqrtf(var + 1e-5f) * ln1_g[lane] + ln1_b[lane];
    }
    __syncthreads();

    // ---- K: stage Wk (qkv rows 32..63, pad 33), compute k into s_kv cols 0..31
    for (int o = t; o < 1024; o += 512)
        s_w[(o >> 5) * 33 + (o & 31)] = qkv_w[32 * 32 + o];
    __syncthreads();
    for (int o = t; o < 2048; o += 512) {
        int hp = o >> 5, j = o & 31;
        float acc = qkv_b[32 + j];
#pragma unroll
        for (int d = 0; d < 32; d++) acc += s_x[hp][d] * s_w[j * 33 + d];
        s_kv[hp * 65 + j] = acc;
    }
    __syncthreads();

    // ---- V: stage Wv (rows 64..95), compute v into s_kv cols 32..63
    for (int o = t; o < 1024; o += 512)
        s_w[(o >> 5) * 33 + (o & 31)] = qkv_w[64 * 32 + o];
    __syncthreads();
    for (int o = t; o < 2048; o += 512) {
        int hp = o >> 5, j = o & 31;
        float acc = qkv_b[64 + j];
#pragma unroll
        for (int d = 0; d < 32; d++) acc += s_x[hp][d] * s_w[j * 33 + d];
        s_kv[hp * 65 + 32 + j] = acc;
    }
    __syncthreads();

    // ---- Q: stage Wq (rows 0..31), compute q into registers, then overwrite s_x
    for (int o = t; o < 1024; o += 512)
        s_w[(o >> 5) * 33 + (o & 31)] = qkv_w[o];
    __syncthreads();
    float qreg[4];
#pragma unroll
    for (int r = 0; r < 4; r++) {
        int hp = wp + r * 16;
        float acc = qkv_b[lane];
#pragma unroll
        for (int d = 0; d < 32; d++) acc += s_x[hp][d] * s_w[lane * 33 + d];
        qreg[r] = acc;
    }
    __syncthreads();   // all reads of LN1-x done
#pragma unroll
    for (int r = 0; r < 4; r++) s_x[wp + r * 16][lane] = qreg[r];
    __syncthreads();

    // attention: warp handles (h,q) pair p; lane covers keys {lane, lane+32}
    for (int c = 0; c < 8; c++) {
        int p = c * 16 + wp;
        int h = p >> 6, q = p & 63;
        int qo = q * 32 + h * 16;           // q in s_x
        int ko = lane * 65 + h * 16;
        int ko2 = (lane + 32) * 65 + h * 16;
        float s0 = 0.f, s1 = 0.f;
#pragma unroll
        for (int dh = 0; dh < 16; dh++) {
            float qq = ((float*)s_x)[qo + dh];
            s0 += qq * s_kv[ko + dh];
            s1 += qq * s_kv[ko2 + dh];
        }
        s0 *= 0.25f; s1 *= 0.25f;
        float m = wredmax(fmaxf(s0, s1));
        float e0 = expf(s0 - m), e1 = expf(s1 - m);
        float inv = 1.f / wredsum(e0 + e1);
        int vo = lane * 65 + 32 + h * 16;
        int vo2 = (lane + 32) * 65 + 32 + h * 16;
#pragma unroll
        for (int dh = 0; dh < 16; dh++) {
            float part = e0 * s_kv[vo + dh] + e1 * s_kv[vo2 + dh];
            float sum = wredsum(part);
            if (lane == dh) s_x[q][h * 16 + dh] = sum * inv;  // overwrites own q slot
        }
    }
    __syncthreads();

    // ---- out proj: stage out_w (32x32, pad 33)
    for (int o = t; o < 1024; o += 512)
        s_w[(o >> 5) * 33 + (o & 31)] = out_w[o];
    __syncthreads();
    for (int o = t; o < 2048; o += 512) {
        int hp = o >> 5, d = o & 31;
        float acc = out_b[d];
#pragma unroll
        for (int e = 0; e < 32; e++) acc += s_x[hp][e] * s_w[d * 33 + e];
        s_feat[hp][d] += acc;
    }
    __syncthreads();

    // LN2 -> s_x
#pragma unroll
    for (int rep = 0; rep < 4; rep++) {
        int hp = rep * 16 + wp;
        float v = s_feat[hp][lane];
        float mu = wredsum(v) * (1.f / 32.f);
        float df = v - mu;
        float var = wredsum(df * df) * (1.f / 32.f);
        s_x[hp][lane] = df * rsqrtf(var + 1e-5f) * ln2_g[lane] + ln2_b[lane];
    }
    __syncthreads();

    // ---- FFN1: stage ffn_w1 (64x32, pad 33); hidden into s_kv (stride 64)
    for (int o = t; o < 2048; o += 512)
        s_w[(o >> 5) * 33 + (o & 31)] = ffn_w1[o];
    __syncthreads();
    for (int o = t; o < 4096; o += 512) {
        int hp = o >> 6, f = o & 63;
        float acc = ffn_b1[f];
#pragma unroll
        for (int d = 0; d < 32; d++) acc += s_x[hp][d] * s_w[f * 33 + d];
        s_kv[hp * 64 + f] = 0.5f * acc * (1.f + erff(acc * 0.70710678118654752f));
    }
    __syncthreads();

    // ---- FFN2: stage ffn_w2 (32x64, pad 65); residual; write g_feat
    for (int o = t; o < 2048; o += 512)
        s_w[(o >> 6) * 65 + (o & 63)] = ffn_w2[o];
    __syncthreads();
    for (int o = t; o < 2048; o += 512) {
        int hp = o >> 5, d = o & 31;
        float acc = ffn_b2[d];
#pragma unroll
        for (int f = 0; f < 64; f++) acc += s_kv[hp * 64 + f] * s_w[d * 65 + f];
        g_feat[bidx * 2048 + o] = s_feat[hp][d] + acc;
    }
}

// ============================================================================
// Kernel 3: heads + merge. One block per (b,hp) slice, 256 threads.
// ============================================================================
__global__ __launch_bounds__(256) void k_merge(
    const float* __restrict__ a, const float* __restrict__ b,
    float* __restrict__ out,
    const float* __restrict__ gate_w, const float* __restrict__ gate_b,
    const float* __restrict__ row_w, const float* __restrict__ row_b,
    const float* __restrict__ col_w, const float* __restrict__ col_b,
    const float* __restrict__ drow_w, const float* __restrict__ drow_b,
    const float* __restrict__ dcol_w, const float* __restrict__ dcol_b,
    const float* __restrict__ delta_scale) {
    const int slice = blockIdx.x;
    const int t = threadIdx.x, lane = t & 31, wp = t >> 5;

    __shared__ float s_feat[32];
    __shared__ float s_r[64], s_c[64], s_dr[64], s_dc[64];
    __shared__ float s_gate;

    if (t < 32) s_feat[t] = g_feat[slice * 32 + t];
    __syncthreads();

    // Heads: 8 warps; warp wp -> matrix (wp>>1), half (wp&1) of 64 outputs.
    {
        const int mat = wp >> 1;
        const float* w; const float* bb; float* dst;
        if (mat == 0)      { w = row_w;  bb = row_b;  dst = s_r; }
        else if (mat == 1) { w = col_w;  bb = col_b;  dst = s_c; }
        else if (mat == 2) { w = drow_w; bb = drow_b; dst = s_dr; }
        else               { w = dcol_w; bb = dcol_b; dst = s_dc; }
        const int g = lane >> 3;
        const int dsub = lane & 7;
        float4 f4 = ((const float4*)s_feat)[dsub];
        const float dscale = (mat == 2) ? *delta_scale : 1.f;
#pragma unroll
        for (int ii = 0; ii < 8; ii++) {
            int i = (wp & 1) * 32 + ii * 4 + g;
            float4 w4 = ((const float4*)w)[i * 8 + dsub];
            float v = w4.x * f4.x + w4.y * f4.y + w4.z * f4.z + w4.w * f4.w;
            v += __shfl_xor_sync(0xffffffffu, v, 1);
            v += __shfl_xor_sync(0xffffffffu, v, 2);
            v += __shfl_xor_sync(0xffffffffu, v, 4);
            if (dsub == 0) dst[i] = (v + bb[i]) * dscale;
        }
        if (wp == 0) {
            float gv = s_feat[lane] * gate_w[lane];
            gv = wredsum(gv);
            if (lane == 0) s_gate = gv + gate_b[0];
        }
    }
    __syncthreads();

    const float4* a4 = (const float4*)a + slice * 1024;
    const float4* b4 = (const float4*)b + slice * 1024;
    float4* o4 = (float4*)out + slice * 1024;
    const float gate = s_gate;

    float4 va[4], vb[4];
#pragma unroll
    for (int k = 0; k < 4; k++) { va[k] = a4[t + k * 256]; vb[k] = b4[t + k * 256]; }
#pragma unroll
    for (int k = 0; k < 4; k++) {
        int p = t + k * 256;
        int i = p >> 4;
        float g = gate + s_r[i];
        float dr = s_dr[i];   // pre-scaled by delta_scale
        float4 c4 = ((const float4*)s_c)[p & 15];
        float4 dc4 = ((const float4*)s_dc)[p & 15];
        float4 r;
        { float m = fsig(g + c4.x); r.x = vb[k].x + m * (va[k].x - vb[k].x) + dr * dc4.x; }
        { float m = fsig(g + c4.y); r.y = vb[k].y + m * (va[k].y - vb[k].y) + dr * dc4.y; }
        { float m = fsig(g + c4.z); r.z = vb[k].z + m * (va[k].z - vb[k].z) + dr * dc4.z; }
        { float m = fsig(g + c4.w); r.w = vb[k].w + m * (va[k].w - vb[k].w) + dr * dc4.w; }
        o4[p] = r;
    }
}

// ============================================================================
extern "C" void kernel_launch(void* const* d_in, const int* in_sizes, int n_in,
                              void* d_out, int out_size) {
    const float* a = (const float*)d_in[0];
    const float* b = (const float*)d_in[1];

    k_stats<<<NBH, 256>>>(a, b);

    k_transformer<<<64, 512>>>(
        (const float*)d_in[2],                          // layer_emb
        (const float*)d_in[3], (const float*)d_in[4],   // in_proj_w, in_proj_b
        (const float*)d_in[5], (const float*)d_in[6],   // ln1_g, ln1_b
        (const float*)d_in[7], (const float*)d_in[8],   // qkv_w, qkv_b
        (const float*)d_in[9], (const float*)d_in[10],  // out_w, out_b
        (const float*)d_in[11], (const float*)d_in[12], // ln2_g, ln2_b
        (const float*)d_in[13], (const float*)d_in[14], // ffn_w1, ffn_b1
        (const float*)d_in[15], (const float*)d_in[16]);// ffn_w2, ffn_b2

    k_merge<<<NBH, 256>>>(
        a, b, (float*)d_out,
        (const float*)d_in[17], (const float*)d_in[18], // gate_w, gate_b
        (const float*)d_in[19], (const float*)d_in[20], // row_w, row_b
        (const float*)d_in[21], (const float*)d_in[22], // col_w, col_b
        (const float*)d_in[23], (const float*)d_in[24], // drow_w, drow_b
        (const float*)d_in[25], (const float*)d_in[26], // dcol_w, dcol_b
        (const float*)d_in[27]);                        // delta_scale
}